// round 5
// baseline (speedup 1.0000x reference)
#include <cuda_runtime.h>

// x[256, 4096, 32] -> out[256, 64, 64, 32]  (GADF)
#define BATCH  256
#define TLEN   4096
#define CH     32
#define PAA    64
#define BINSZ  64   // TLEN / PAA
#define SEGS   8    // reduce-kernel segments per batch
#define CHUNKS 8
#define CB     (BATCH / CHUNKS)   // 32 batches per chunk

// Inter-kernel scratch (small; L2-resident).
__device__ float g_binsum[BATCH][PAA][CH];   // 2 MB
__device__ float g_pmin[BATCH][SEGS][CH];    // 256 KB
__device__ float g_pmax[BATCH][SEGS][CH];    // 256 KB

// ---------------------------------------------------------------------------
// K1: pure read stream for one chunk. CB*SEGS = 256 blocks x 256 threads.
// Block -> (b = b0 + blk>>3, seg s = blk&7); warp w reduces bin 8s+w.
// lane -> (t_off = lane>>3, c4 = (lane&7)*4); 16 x LDG.128 per lane.
// ---------------------------------------------------------------------------
__global__ __launch_bounds__(256)
void gaf_reduce_kernel(const float* __restrict__ x, int b0) {
    __shared__ float smn[8][36];
    __shared__ float smx[8][36];

    const int tid   = threadIdx.x;
    const int lane  = tid & 31;
    const int warp  = tid >> 5;          // 0..7
    const int t_off = lane >> 3;         // 0..3
    const int c4    = (lane & 7) * 4;
    const int b     = b0 + (blockIdx.x >> 3);
    const int s     = blockIdx.x & 7;
    const int bin   = 8 * s + warp;

    const float* base = x + (size_t)b * (TLEN * CH)
                          + (size_t)(bin * BINSZ + t_off) * CH + c4;

    float4 sum  = {0, 0, 0, 0};
    float4 vmin = { 3.4e38f,  3.4e38f,  3.4e38f,  3.4e38f};
    float4 vmax = {-3.4e38f, -3.4e38f, -3.4e38f, -3.4e38f};

    #pragma unroll
    for (int k = 0; k < 16; ++k) {
        float4 v = __ldcs((const float4*)(base + (size_t)(4 * k) * CH));
        sum.x += v.x; sum.y += v.y; sum.z += v.z; sum.w += v.w;
        vmin.x = fminf(vmin.x, v.x); vmin.y = fminf(vmin.y, v.y);
        vmin.z = fminf(vmin.z, v.z); vmin.w = fminf(vmin.w, v.w);
        vmax.x = fmaxf(vmax.x, v.x); vmax.y = fmaxf(vmax.y, v.y);
        vmax.z = fmaxf(vmax.z, v.z); vmax.w = fmaxf(vmax.w, v.w);
    }

    #pragma unroll
    for (int o = 8; o <= 16; o <<= 1) {
        sum.x += __shfl_xor_sync(~0u, sum.x, o); sum.y += __shfl_xor_sync(~0u, sum.y, o);
        sum.z += __shfl_xor_sync(~0u, sum.z, o); sum.w += __shfl_xor_sync(~0u, sum.w, o);
        vmin.x = fminf(vmin.x, __shfl_xor_sync(~0u, vmin.x, o));
        vmin.y = fminf(vmin.y, __shfl_xor_sync(~0u, vmin.y, o));
        vmin.z = fminf(vmin.z, __shfl_xor_sync(~0u, vmin.z, o));
        vmin.w = fminf(vmin.w, __shfl_xor_sync(~0u, vmin.w, o));
        vmax.x = fmaxf(vmax.x, __shfl_xor_sync(~0u, vmax.x, o));
        vmax.y = fmaxf(vmax.y, __shfl_xor_sync(~0u, vmax.y, o));
        vmax.z = fmaxf(vmax.z, __shfl_xor_sync(~0u, vmax.z, o));
        vmax.w = fmaxf(vmax.w, __shfl_xor_sync(~0u, vmax.w, o));
    }

    if (t_off == 0) {  // lanes 0..7 hold channels c4..c4+3
        *(float4*)&g_binsum[b][bin][c4] = sum;
        *(float4*)&smn[warp][c4] = vmin;
        *(float4*)&smx[warp][c4] = vmax;
    }
    __syncthreads();

    if (tid < CH) {
        float m = smn[0][tid], M = smx[0][tid];
        #pragma unroll
        for (int w = 1; w < 8; ++w) {
            m = fminf(m, smn[w][tid]);
            M = fmaxf(M, smx[w][tid]);
        }
        g_pmin[b][s][tid] = m;
        g_pmax[b][s][tid] = M;
    }
}

// ---------------------------------------------------------------------------
// K2: pure write stream for one chunk. CB*2 = 64 blocks x 512 threads.
// Block -> (b = b0 + blk>>1, i-half ih = blk&1 covering 32 i-rows = 256 KB).
// Builds p,y in SMEM from L2-resident scratch, then:
//   out[b,i,j,c] = y_i*p_j - p_i*y_j, STG.128, 512B contiguous per warp.
// Thread -> (j = tid>>3 covers all 64 j, c4 = (tid&7)*4); loops 32 i's.
// ---------------------------------------------------------------------------
__global__ __launch_bounds__(512)
void gaf_produce_kernel(float* __restrict__ out, int b0) {
    __shared__ float sp[PAA][CH];    // p
    __shared__ float sy[PAA][CH];    // y
    __shared__ float smin[CH];
    __shared__ float sinv[CH];

    const int tid = threadIdx.x;
    const int b   = b0 + (blockIdx.x >> 1);
    const int ih  = blockIdx.x & 1;

    if (tid < CH) {
        float m = g_pmin[b][0][tid], M = g_pmax[b][0][tid];
        #pragma unroll
        for (int s = 1; s < SEGS; ++s) {
            m = fminf(m, g_pmin[b][s][tid]);
            M = fmaxf(M, g_pmax[b][s][tid]);
        }
        smin[tid] = m;
        sinv[tid] = 1.0f / (M - m);
    }
    __syncthreads();

    #pragma unroll
    for (int idx = tid; idx < PAA * CH; idx += 512) {
        int c = idx & (CH - 1);
        float pv = ((&g_binsum[b][0][0])[idx] * (1.0f / BINSZ) - smin[c]) * sinv[c];
        (&sp[0][0])[idx] = pv;
        (&sy[0][0])[idx] = sqrtf(fmaxf(0.0f, 1.0f - pv * pv));
    }
    __syncthreads();

    const int c4 = (tid & 7) * 4;
    const int j  = tid >> 3;                    // 0..63

    const float4 pj = *(const float4*)&sp[j][c4];
    const float4 yj = *(const float4*)&sy[j][c4];

    float* ob = out + (size_t)b * (PAA * PAA * CH) + (size_t)j * CH + c4;
    #pragma unroll 8
    for (int ii = 0; ii < 32; ++ii) {
        const int i = ih * 32 + ii;
        const float4 pi = *(const float4*)&sp[i][c4];   // 8 addrs, broadcast x4
        const float4 yi = *(const float4*)&sy[i][c4];
        float4 o;
        o.x = yi.x * pj.x - pi.x * yj.x;
        o.y = yi.y * pj.y - pi.y * yj.y;
        o.z = yi.z * pj.z - pi.z * yj.z;
        o.w = yi.w * pj.w - pi.w * yj.w;
        __stcs((float4*)(ob + (size_t)i * (PAA * CH)), o);
    }
}

extern "C" void kernel_launch(void* const* d_in, const int* in_sizes, int n_in,
                              void* d_out, int out_size) {
    const float* x = (const float*)d_in[0];
    float* out = (float*)d_out;

    // One-time creation of the second stream + fork/join events (no device
    // memory involved; created on the first (uncaptured) correctness call,
    // reused identically on every call including graph capture).
    static cudaStream_t s2 = nullptr;
    static cudaEvent_t evk[CHUNKS];
    static cudaEvent_t evJoin = nullptr;
    if (s2 == nullptr) {
        cudaStreamCreateWithFlags(&s2, cudaStreamNonBlocking);
        for (int c = 0; c < CHUNKS; ++c)
            cudaEventCreateWithFlags(&evk[c], cudaEventDisableTiming);
        cudaEventCreateWithFlags(&evJoin, cudaEventDisableTiming);
    }

    // Pipelined chunks: K1 (reads) on the capture stream, K2 (writes) on s2,
    // gated per-chunk by events. K2(c) overlaps K1(c+1..): the HBM write
    // stream runs concurrently with the read stream.
    for (int c = 0; c < CHUNKS; ++c) {
        gaf_reduce_kernel<<<CB * SEGS, 256>>>(x, c * CB);
        cudaEventRecord(evk[c], 0);
        cudaStreamWaitEvent(s2, evk[c], 0);
        gaf_produce_kernel<<<CB * 2, 512, 0, s2>>>(out, c * CB);
    }
    cudaEventRecord(evJoin, s2);
    cudaStreamWaitEvent(0, evJoin, 0);
}

// round 6
// speedup vs baseline: 1.3356x; 1.3356x over previous
#include <cuda_runtime.h>
#include <cstdint>

// x[256, 4096, 32] -> out[256, 64, 64, 32]  (GADF)
#define BATCH 256
#define TLEN  4096
#define CH    32
#define PAA   64
#define BINSZ 64      // TLEN / PAA
#define NBUF  4       // TMA staging buffers
#define CHUNK_FLOATS 4096           // 16 KB = 2 output i-rows
#define CHUNK_BYTES  (CHUNK_FLOATS * 4)
#define NCHUNK 32                   // 32 chunks x 16 KB = 512 KB per batch

// Dynamic SMEM layout (floats):
//  [0,16384)      4 x 4096 staging buffers (64 KB)
//  [16384,18432)  sp[64][32]   (p)
//  [18432,20480)  sy[64][32]   (y)
//  [20480,20512)  smin[32]
//  [20512,20544)  smax[32]
//  [20544,21696)  smmn[32][36]
//  [21696,22848)  smmx[32][36]
#define SMEM_FLOATS 22848
#define SMEM_BYTES  (SMEM_FLOATS * 4)

__global__ __launch_bounds__(1024, 2)
void gaf_gadf_kernel(const float* __restrict__ x, float* __restrict__ out) {
    extern __shared__ float smem[];
    float* buf          = smem;
    float (*sp)[CH]     = (float(*)[CH])(smem + 16384);
    float (*sy)[CH]     = (float(*)[CH])(smem + 18432);
    float* smin         = smem + 20480;
    float* smax         = smem + 20512;
    float (*smmn)[36]   = (float(*)[36])(smem + 20544);
    float (*smmx)[36]   = (float(*)[36])(smem + 21696);

    const int tid   = threadIdx.x;
    const int lane  = tid & 31;
    const int warp  = tid >> 5;        // 0..31
    const int t_off = lane >> 3;       // 0..3
    const int c4    = (lane & 7) * 4;  // channel group start
    const int b     = blockIdx.x;

    const float* xb = x + (size_t)b * (TLEN * CH);

    // ---------------- Read phase: warp w owns t in [128w,128w+128) --------
    {
        const float* base = xb + (size_t)(128 * warp + t_off) * CH + c4;
        float4 s0 = {0,0,0,0}, s1 = {0,0,0,0};
        float4 vmin = { 3.4e38f,  3.4e38f,  3.4e38f,  3.4e38f};
        float4 vmax = {-3.4e38f, -3.4e38f, -3.4e38f, -3.4e38f};

        #pragma unroll 8
        for (int k = 0; k < 16; ++k) {
            float4 v = *(const float4*)(base + (size_t)(4 * k) * CH);
            s0.x += v.x; s0.y += v.y; s0.z += v.z; s0.w += v.w;
            vmin.x = fminf(vmin.x, v.x); vmin.y = fminf(vmin.y, v.y);
            vmin.z = fminf(vmin.z, v.z); vmin.w = fminf(vmin.w, v.w);
            vmax.x = fmaxf(vmax.x, v.x); vmax.y = fmaxf(vmax.y, v.y);
            vmax.z = fmaxf(vmax.z, v.z); vmax.w = fmaxf(vmax.w, v.w);
        }
        #pragma unroll 8
        for (int k = 16; k < 32; ++k) {
            float4 v = *(const float4*)(base + (size_t)(4 * k) * CH);
            s1.x += v.x; s1.y += v.y; s1.z += v.z; s1.w += v.w;
            vmin.x = fminf(vmin.x, v.x); vmin.y = fminf(vmin.y, v.y);
            vmin.z = fminf(vmin.z, v.z); vmin.w = fminf(vmin.w, v.w);
            vmax.x = fmaxf(vmax.x, v.x); vmax.y = fmaxf(vmax.y, v.y);
            vmax.z = fmaxf(vmax.z, v.z); vmax.w = fmaxf(vmax.w, v.w);
        }

        // Collapse the 4 t_off copies (lanes xor 8, 16).
        #pragma unroll
        for (int o = 8; o <= 16; o <<= 1) {
            s0.x += __shfl_xor_sync(~0u, s0.x, o); s0.y += __shfl_xor_sync(~0u, s0.y, o);
            s0.z += __shfl_xor_sync(~0u, s0.z, o); s0.w += __shfl_xor_sync(~0u, s0.w, o);
            s1.x += __shfl_xor_sync(~0u, s1.x, o); s1.y += __shfl_xor_sync(~0u, s1.y, o);
            s1.z += __shfl_xor_sync(~0u, s1.z, o); s1.w += __shfl_xor_sync(~0u, s1.w, o);
            vmin.x = fminf(vmin.x, __shfl_xor_sync(~0u, vmin.x, o));
            vmin.y = fminf(vmin.y, __shfl_xor_sync(~0u, vmin.y, o));
            vmin.z = fminf(vmin.z, __shfl_xor_sync(~0u, vmin.z, o));
            vmin.w = fminf(vmin.w, __shfl_xor_sync(~0u, vmin.w, o));
            vmax.x = fmaxf(vmax.x, __shfl_xor_sync(~0u, vmax.x, o));
            vmax.y = fmaxf(vmax.y, __shfl_xor_sync(~0u, vmax.y, o));
            vmax.z = fmaxf(vmax.z, __shfl_xor_sync(~0u, vmax.z, o));
            vmax.w = fmaxf(vmax.w, __shfl_xor_sync(~0u, vmax.w, o));
        }
        if (t_off == 0) {  // lanes 0..7: channels c4..c4+3
            *(float4*)&sp[2 * warp + 0][c4] = s0;
            *(float4*)&sp[2 * warp + 1][c4] = s1;
            *(float4*)&smmn[warp][c4] = vmin;
            *(float4*)&smmx[warp][c4] = vmax;
        }
    }
    __syncthreads();

    // ---------------- Final min/max over 32 warps -------------------------
    if (tid < CH) {
        float m = smmn[0][tid], M = smmx[0][tid];
        #pragma unroll
        for (int w = 1; w < 32; ++w) {
            m = fminf(m, smmn[w][tid]);
            M = fmaxf(M, smmx[w][tid]);
        }
        smin[tid] = m;
        smax[tid] = M;
    }
    __syncthreads();

    // ---------------- p and y ---------------------------------------------
    {
        int idx = tid;
        #pragma unroll
        for (int r = 0; r < 2; ++r, idx += 1024) {
            int c = idx & (CH - 1);
            float mn  = smin[c];
            float inv = 1.0f / (smax[c] - mn);
            float pv  = ((&sp[0][0])[idx] * (1.0f / BINSZ) - mn) * inv;
            (&sp[0][0])[idx] = pv;
            (&sy[0][0])[idx] = sqrtf(fmaxf(0.0f, 1.0f - pv * pv));
        }
    }
    __syncthreads();

    // ---------------- Write phase: STS into staging + TMA bulk store ------
    // chunk k = output i-rows {2k, 2k+1} (16 KB). thread -> (i_off, j, c4).
    const int i_off = tid >> 9;            // 0 or 1
    const int j     = (tid >> 3) & 63;

    const float4 pj = *(const float4*)&sp[j][c4];
    const float4 yj = *(const float4*)&sy[j][c4];

    char* ob = (char*)(out + (size_t)b * (PAA * PAA * CH));
    const int soff = (i_off * PAA + j) * CH + c4;   // float offset in chunk

    #pragma unroll 1
    for (int k = 0; k < NCHUNK; ++k) {
        // Recycle: buffer k%4 is free once group k-4 completed (<=3 pending).
        if (k >= NBUF) {
            if (tid == 0)
                asm volatile("cp.async.bulk.wait_group %0;" :: "n"(NBUF - 1) : "memory");
            __syncthreads();
        }

        const int i = 2 * k + i_off;
        const float4 pi = *(const float4*)&sp[i][c4];
        const float4 yi = *(const float4*)&sy[i][c4];
        float4 o;
        o.x = yi.x * pj.x - pi.x * yj.x;
        o.y = yi.y * pj.y - pi.y * yj.y;
        o.z = yi.z * pj.z - pi.z * yj.z;
        o.w = yi.w * pj.w - pi.w * yj.w;
        *(float4*)(buf + (k & (NBUF - 1)) * CHUNK_FLOATS + soff) = o;  // STS.128
        __syncthreads();

        if (tid == 0) {
            asm volatile("fence.proxy.async.shared::cta;" ::: "memory");
            uint32_t saddr = (uint32_t)__cvta_generic_to_shared(
                                 buf + (k & (NBUF - 1)) * CHUNK_FLOATS);
            asm volatile(
                "cp.async.bulk.global.shared::cta.bulk_group [%0], [%1], %2;"
                :: "l"(ob + (size_t)k * CHUNK_BYTES), "r"(saddr), "n"(CHUNK_BYTES)
                : "memory");
            asm volatile("cp.async.bulk.commit_group;" ::: "memory");
        }
    }

    // Drain all outstanding bulk stores before exit.
    if (tid == 0)
        asm volatile("cp.async.bulk.wait_group 0;" ::: "memory");
}

extern "C" void kernel_launch(void* const* d_in, const int* in_sizes, int n_in,
                              void* d_out, int out_size) {
    const float* x = (const float*)d_in[0];
    float* out = (float*)d_out;
    cudaFuncSetAttribute(gaf_gadf_kernel,
                         cudaFuncAttributeMaxDynamicSharedMemorySize, SMEM_BYTES);
    gaf_gadf_kernel<<<BATCH, 1024, SMEM_BYTES>>>(x, out);
}